// round 2
// baseline (speedup 1.0000x reference)
#include <cuda_runtime.h>

#define NC 4000
#define ND 2000
#define FC 2048
#define FD 1024
#define NT 6000

// output region offsets (floats)
#define OUT0 ((size_t)0)         // agg_cell_lp [4000,2000]
#define OUT1 ((size_t)8000000)   // agg_drug_lp [2000,4000]
#define OUT2 ((size_t)16000000)  // agg_adj_lp  [6000,6000]
#define OUT3 ((size_t)52000000)  // self_cell_lp diag [4000,4000]
#define OUT4 ((size_t)68000000)  // self_drug_lp diag [2000,2000]
#define OUT5 ((size_t)72000000)  // self_adj_lp  diag [6000,6000]

// scratch layout (floats)
#define S_C        ((size_t)0)          // 16,000,000  C_lin (cell gemm out, no bias)
#define S_D        ((size_t)16000000)   //  4,000,000  D_lin
#define S_ADJT     ((size_t)20000000)   //  8,000,000  adj transposed [2000,4000]
#define S_PSUM     ((size_t)28000000)   //    128,000  partial col sums
#define S_PSQ      ((size_t)28128000)   //    128,000  partial col sumsq
#define S_RSADJ    ((size_t)28256000)   // 4000 rowsum(adj)
#define S_CSADJ    ((size_t)28260000)   // 2000 colsum(adj)
#define S_MUC      ((size_t)28262000)   // 4000
#define S_ISC      ((size_t)28266000)   // 4000
#define S_MUD      ((size_t)28270000)   // 2000
#define S_ISD      ((size_t)28272000)   // 2000
#define S_RSC      ((size_t)28274000)   // 4000 rowsum of BN'd cell
#define S_RSD      ((size_t)28278000)   // 2000 rowsum of BN'd drug
#define S_DX       ((size_t)28280000)   // 4000
#define S_DY       ((size_t)28284000)   // 2000
#define S_DX1      ((size_t)28286000)   // 6000
#define S_DY1      ((size_t)28292000)   // 6000
#define S_TOTAL    ((size_t)28298000)

__device__ float g_scratch[S_TOTAL];

// ---------------------------------------------------------------------------
// zero a float region (replaces cudaMemsetAsync for capture-node uniformity)
// ---------------------------------------------------------------------------
__global__ void memzero_k(float* __restrict__ p, size_t n4)
{
    size_t i = (size_t)blockIdx.x * blockDim.x + threadIdx.x;
    if (i < n4) {
        float4 z = make_float4(0.f, 0.f, 0.f, 0.f);
        reinterpret_cast<float4*>(p)[i] = z;
    }
}

// ---------------------------------------------------------------------------
// NT SGEMM: C[m,n] = sum_k A[m,k]*B[n,k].  A:[M,K] B:[N,K] row-major.
// 128x128x16 tile, 8x8 microtile, 256 threads.
// ---------------------------------------------------------------------------
__global__ __launch_bounds__(256) void sgemm_nt(
    const float* __restrict__ A, const float* __restrict__ B,
    float* __restrict__ C, int M, int N, int K)
{
    __shared__ float As[16][128];
    __shared__ float Bs[16][128];

    const int tid = threadIdx.x;
    const int bm = blockIdx.y * 128;
    const int bn = blockIdx.x * 128;
    const int tx = tid & 15;
    const int ty = tid >> 4;

    float acc[8][8];
#pragma unroll
    for (int i = 0; i < 8; i++)
#pragma unroll
        for (int j = 0; j < 8; j++) acc[i][j] = 0.0f;

    for (int k0 = 0; k0 < K; k0 += 16) {
        // load 128x16 tiles of A and B (transposed into smem as [k][m])
#pragma unroll
        for (int l = 0; l < 2; l++) {
            int f   = tid + l * 256;     // 0..511 (float4 index)
            int row = f >> 2;            // 0..127
            int kq  = (f & 3) << 2;      // 0,4,8,12
            float4 av = make_float4(0.f, 0.f, 0.f, 0.f);
            int gr = bm + row;
            if (gr < M)
                av = *reinterpret_cast<const float4*>(A + (size_t)gr * K + k0 + kq);
            As[kq + 0][row] = av.x; As[kq + 1][row] = av.y;
            As[kq + 2][row] = av.z; As[kq + 3][row] = av.w;

            float4 bv = make_float4(0.f, 0.f, 0.f, 0.f);
            int gc = bn + row;
            if (gc < N)
                bv = *reinterpret_cast<const float4*>(B + (size_t)gc * K + k0 + kq);
            Bs[kq + 0][row] = bv.x; Bs[kq + 1][row] = bv.y;
            Bs[kq + 2][row] = bv.z; Bs[kq + 3][row] = bv.w;
        }
        __syncthreads();

#pragma unroll
        for (int kk = 0; kk < 16; kk++) {
            float4 a0 = *reinterpret_cast<const float4*>(&As[kk][ty * 8]);
            float4 a1 = *reinterpret_cast<const float4*>(&As[kk][ty * 8 + 4]);
            float4 b0 = *reinterpret_cast<const float4*>(&Bs[kk][tx * 8]);
            float4 b1 = *reinterpret_cast<const float4*>(&Bs[kk][tx * 8 + 4]);
            float ra[8] = {a0.x, a0.y, a0.z, a0.w, a1.x, a1.y, a1.z, a1.w};
            float rb[8] = {b0.x, b0.y, b0.z, b0.w, b1.x, b1.y, b1.z, b1.w};
#pragma unroll
            for (int i = 0; i < 8; i++)
#pragma unroll
                for (int j = 0; j < 8; j++)
                    acc[i][j] += ra[i] * rb[j];
        }
        __syncthreads();
    }

#pragma unroll
    for (int i = 0; i < 8; i++) {
        int r = bm + ty * 8 + i;
        if (r < M) {
            float* crow = C + (size_t)r * N;
#pragma unroll
            for (int j0 = 0; j0 < 8; j0 += 4) {
                int c = bn + tx * 8 + j0;
                if (c < N) {
                    float4 v = make_float4(acc[i][j0], acc[i][j0 + 1],
                                           acc[i][j0 + 2], acc[i][j0 + 3]);
                    *reinterpret_cast<float4*>(crow + c) = v;
                }
            }
        }
    }
}

// ---------------------------------------------------------------------------
// row reduce: out[row] = sum_j M[row,j]
// ---------------------------------------------------------------------------
__global__ void rowreduce_k(const float* __restrict__ Mp, int ncols, float* __restrict__ out)
{
    int row = blockIdx.x;
    const float* p = Mp + (size_t)row * ncols;
    float s = 0.0f;
    for (int j = threadIdx.x; j < ncols; j += blockDim.x) s += p[j];
    __shared__ float sh[256];
    sh[threadIdx.x] = s;
    __syncthreads();
    for (int st = 128; st > 0; st >>= 1) {
        if (threadIdx.x < st) sh[threadIdx.x] += sh[threadIdx.x + st];
        __syncthreads();
    }
    if (threadIdx.x == 0) out[row] = sh[0];
}

// weighted row reduce over BN'd matrix: out[row]=sum_j gamma[j]*isd[j]*(M-mu[j])+beta[j]
__global__ void rowsum_bn_k(const float* __restrict__ Mp, int ncols,
                            const float* __restrict__ gamma, const float* __restrict__ isd,
                            const float* __restrict__ mu, const float* __restrict__ beta,
                            float* __restrict__ out)
{
    int row = blockIdx.x;
    const float* p = Mp + (size_t)row * ncols;
    float s = 0.0f;
    for (int j = threadIdx.x; j < ncols; j += blockDim.x)
        s += gamma[j] * isd[j] * (p[j] - mu[j]) + beta[j];
    __shared__ float sh[256];
    sh[threadIdx.x] = s;
    __syncthreads();
    for (int st = 128; st > 0; st >>= 1) {
        if (threadIdx.x < st) sh[threadIdx.x] += sh[threadIdx.x + st];
        __syncthreads();
    }
    if (threadIdx.x == 0) out[row] = sh[0];
}

// ---------------------------------------------------------------------------
// column partial sums + sumsq over a row range (deterministic, no atomics)
// ---------------------------------------------------------------------------
__global__ void colstats_partial_k(const float* __restrict__ Mp, int nrows, int ncols,
                                   int rowsPerBlock, float* __restrict__ psum,
                                   float* __restrict__ psq)
{
    int j = blockIdx.x * blockDim.x + threadIdx.x;
    if (j >= ncols) return;
    int r0 = blockIdx.y * rowsPerBlock;
    int r1 = min(r0 + rowsPerBlock, nrows);
    float s = 0.0f, q = 0.0f;
    for (int i = r0; i < r1; i++) {
        float v = Mp[(size_t)i * ncols + j];
        s += v;
        q += v * v;
    }
    psum[(size_t)blockIdx.y * ncols + j] = s;
    psq [(size_t)blockIdx.y * ncols + j] = q;
}

__global__ void colstats_final_k(int nparts, int ncols, int nrows,
                                 const float* __restrict__ psum, const float* __restrict__ psq,
                                 float* __restrict__ mu, float* __restrict__ isd)
{
    int j = blockIdx.x * blockDim.x + threadIdx.x;
    if (j >= ncols) return;
    float s = 0.0f, q = 0.0f;
    for (int p = 0; p < nparts; p++) {
        s += psum[(size_t)p * ncols + j];
        q += psq [(size_t)p * ncols + j];
    }
    float m = s / (float)nrows;
    float var = q / (float)nrows - m * m;
    mu[j] = m;
    isd[j] = rsqrtf(var + 1e-5f);
}

__global__ void colsum_final_k(int nparts, int ncols, const float* __restrict__ psum,
                               float* __restrict__ out)
{
    int j = blockIdx.x * blockDim.x + threadIdx.x;
    if (j >= ncols) return;
    float s = 0.0f;
    for (int p = 0; p < nparts; p++) s += psum[(size_t)p * ncols + j];
    out[j] = s;
}

// ---------------------------------------------------------------------------
// transpose adj [4000,2000] -> adjT [2000,4000]
// ---------------------------------------------------------------------------
__global__ void transpose_k(const float* __restrict__ in, float* __restrict__ out,
                            int rows, int cols)
{
    __shared__ float tile[32][33];
    int c = blockIdx.x * 32 + threadIdx.x;
    int r = blockIdx.y * 32 + threadIdx.y;
#pragma unroll
    for (int i = 0; i < 32; i += 8)
        if (r + i < rows && c < cols)
            tile[threadIdx.y + i][threadIdx.x] = in[(size_t)(r + i) * cols + c];
    __syncthreads();
    int oc = blockIdx.y * 32 + threadIdx.x;    // row-index of input
    int orow = blockIdx.x * 32 + threadIdx.y;  // col-index of input
#pragma unroll
    for (int i = 0; i < 32; i += 8)
        if (orow + i < cols && oc < rows)
            out[(size_t)(orow + i) * rows + oc] = tile[threadIdx.x][threadIdx.y + i];
}

// ---------------------------------------------------------------------------
// finalize scalar vectors + diag writes
// ---------------------------------------------------------------------------
__global__ void finalize_k(const float* __restrict__ beta_c, const float* __restrict__ beta_d,
                           const float* __restrict__ rs_adj, const float* __restrict__ cs_adj,
                           const float* __restrict__ rs_c, const float* __restrict__ rs_d,
                           float* __restrict__ dx, float* __restrict__ dy,
                           float* __restrict__ dx1, float* __restrict__ dy1,
                           float* __restrict__ out)
{
    int r = blockIdx.x * blockDim.x + threadIdx.x;
    if (r >= NT) return;
    float rsA, csA;
    if (r < NC) {
        float ra = rs_adj[r];
        dx[r] = rsqrtf(ra + 1.0f);
        rsA = rs_c[r] + ra;                       // rowsum(A) row r
        csA = (float)NC * beta_c[r] + ra;         // colsum(A) col r (colsum of BN'd cell = n*beta)
    } else {
        int d = r - NC;
        float ca = cs_adj[d];
        dy[d] = rsqrtf(ca + 1.0f);
        rsA = ca + rs_d[d];
        csA = ca + (float)ND * beta_d[d];
    }
    dx1[r] = rsqrtf(rsA + 1.0f);
    dy1[r] = rsqrtf(csA + 1.0f);
    float dval = 1.0f / (rsA + 1.0f) + 1.0f;
    out[OUT5 + (size_t)r * (NT + 1)] = dval;      // self_adj_lp diag
    if (r < NC) out[OUT3 + (size_t)r * (NC + 1)] = dval;        // self_cell_lp diag
    else        out[OUT4 + (size_t)(r - NC) * (ND + 1)] = dval; // self_drug_lp diag
}

// ---------------------------------------------------------------------------
// output assembly kernels
// ---------------------------------------------------------------------------
// out[i*cols+j] = dr[i] * m[i*cols+j] * dc[j]
__global__ void scale_mat_k(const float* __restrict__ m, const float* __restrict__ dr,
                            const float* __restrict__ dc, int cols,
                            float* __restrict__ out)
{
    int j = blockIdx.x * blockDim.x + threadIdx.x;
    int i = blockIdx.y;
    if (j < cols)
        out[(size_t)i * cols + j] = dr[i] * m[(size_t)i * cols + j] * dc[j];
}

__global__ void agg_TL_k(const float* __restrict__ Cm, const float* __restrict__ mu,
                         const float* __restrict__ isd, const float* __restrict__ gamma,
                         const float* __restrict__ beta, const float* __restrict__ dx1,
                         const float* __restrict__ dy1, float* __restrict__ out)
{
    int j = blockIdx.x * blockDim.x + threadIdx.x;
    int r = blockIdx.y;
    if (j >= NC) return;
    float v = gamma[j] * (Cm[(size_t)r * NC + j] - mu[j]) * isd[j] + beta[j];
    out[OUT2 + (size_t)r * NT + j] = dx1[r] * dy1[j] * v;
}

__global__ void agg_TR_k(const float* __restrict__ adj, const float* __restrict__ dx1,
                         const float* __restrict__ dy1, float* __restrict__ out)
{
    int j = blockIdx.x * blockDim.x + threadIdx.x;
    int r = blockIdx.y;
    if (j >= ND) return;
    out[OUT2 + (size_t)r * NT + NC + j] = dx1[r] * dy1[NC + j] * adj[(size_t)r * ND + j];
}

__global__ void agg_BL_k(const float* __restrict__ adjT, const float* __restrict__ dx1,
                         const float* __restrict__ dy1, float* __restrict__ out)
{
    int j = blockIdx.x * blockDim.x + threadIdx.x;
    int d = blockIdx.y;
    if (j >= NC) return;
    out[OUT2 + (size_t)(NC + d) * NT + j] = dx1[NC + d] * dy1[j] * adjT[(size_t)d * NC + j];
}

__global__ void agg_BR_k(const float* __restrict__ Dm, const float* __restrict__ mu,
                         const float* __restrict__ isd, const float* __restrict__ gamma,
                         const float* __restrict__ beta, const float* __restrict__ dx1,
                         const float* __restrict__ dy1, float* __restrict__ out)
{
    int j = blockIdx.x * blockDim.x + threadIdx.x;
    int d = blockIdx.y;
    if (j >= ND) return;
    float v = gamma[j] * (Dm[(size_t)d * ND + j] - mu[j]) * isd[j] + beta[j];
    out[OUT2 + (size_t)(NC + d) * NT + NC + j] = dx1[NC + d] * dy1[NC + j] * v;
}

// ---------------------------------------------------------------------------
extern "C" void kernel_launch(void* const* d_in, const int* in_sizes, int n_in,
                              void* d_out, int out_size)
{
    const float* adj       = (const float*)d_in[0];
    const float* cell_feat = (const float*)d_in[1];
    const float* drug_feat = (const float*)d_in[2];
    const float* W_cell    = (const float*)d_in[3];
    const float* W_drug    = (const float*)d_in[5];
    const float* gamma_c   = (const float*)d_in[7];
    const float* beta_c    = (const float*)d_in[8];
    const float* gamma_d   = (const float*)d_in[9];
    const float* beta_d    = (const float*)d_in[10];
    float* out = (float*)d_out;

    float* sc = nullptr;
    cudaGetSymbolAddress((void**)&sc, g_scratch);

    float* pC     = sc + S_C;
    float* pD     = sc + S_D;
    float* pAdjT  = sc + S_ADJT;
    float* pPsum  = sc + S_PSUM;
    float* pPsq   = sc + S_PSQ;
    float* pRsAdj = sc + S_RSADJ;
    float* pCsAdj = sc + S_CSADJ;
    float* pMuC   = sc + S_MUC;
    float* pIsC   = sc + S_ISC;
    float* pMuD   = sc + S_MUD;
    float* pIsD   = sc + S_ISD;
    float* pRsC   = sc + S_RSC;
    float* pRsD   = sc + S_RSD;
    float* pDx    = sc + S_DX;
    float* pDy    = sc + S_DY;
    float* pDx1   = sc + S_DX1;
    float* pDy1   = sc + S_DY1;

    // zero the diag output regions (56M floats = 14M float4) — plain kernels,
    // not cudaMemsetAsync, so every captured node is an ordinary launch
    {
        size_t n3 = ((size_t)NC * NC) / 4, n4 = ((size_t)ND * ND) / 4, n5 = ((size_t)NT * NT) / 4;
        memzero_k<<<(unsigned)((n3 + 255) / 256), 256>>>(out + OUT3, n3);
        memzero_k<<<(unsigned)((n4 + 255) / 256), 256>>>(out + OUT4, n4);
        memzero_k<<<(unsigned)((n5 + 255) / 256), 256>>>(out + OUT5, n5);
    }

    // adj reductions
    rowreduce_k<<<NC, 256>>>(adj, ND, pRsAdj);
    colstats_partial_k<<<dim3((ND + 255) / 256, 16), 256>>>(adj, NC, ND, 250, pPsum, pPsq);
    colsum_final_k<<<(ND + 255) / 256, 256>>>(16, ND, pPsum, pCsAdj);

    // adj transpose
    transpose_k<<<dim3((ND + 31) / 32, (NC + 31) / 32), dim3(32, 8)>>>(adj, pAdjT, NC, ND);

    // cell GEMM + BN stats + BN rowsums
    sgemm_nt<<<dim3((NC + 127) / 128, (NC + 127) / 128), 256>>>(cell_feat, W_cell, pC, NC, NC, FC);
    colstats_partial_k<<<dim3((NC + 255) / 256, 20), 256>>>(pC, NC, NC, 200, pPsum, pPsq);
    colstats_final_k<<<(NC + 255) / 256, 256>>>(20, NC, NC, pPsum, pPsq, pMuC, pIsC);
    rowsum_bn_k<<<NC, 256>>>(pC, NC, gamma_c, pIsC, pMuC, beta_c, pRsC);

    // drug GEMM + BN stats + BN rowsums
    sgemm_nt<<<dim3((ND + 127) / 128, (ND + 127) / 128), 256>>>(drug_feat, W_drug, pD, ND, ND, FD);
    colstats_partial_k<<<dim3((ND + 255) / 256, 10), 256>>>(pD, ND, ND, 200, pPsum, pPsq);
    colstats_final_k<<<(ND + 255) / 256, 256>>>(10, ND, ND, pPsum, pPsq, pMuD, pIsD);
    rowsum_bn_k<<<ND, 256>>>(pD, ND, gamma_d, pIsD, pMuD, beta_d, pRsD);

    // scalars + diagonals
    finalize_k<<<(NT + 255) / 256, 256>>>(beta_c, beta_d, pRsAdj, pCsAdj, pRsC, pRsD,
                                          pDx, pDy, pDx1, pDy1, out);

    // agg_cell_lp / agg_drug_lp
    scale_mat_k<<<dim3((ND + 255) / 256, NC), 256>>>(adj, pDx, pDy, ND, out + OUT0);
    scale_mat_k<<<dim3((NC + 255) / 256, ND), 256>>>(pAdjT, pDy, pDx, NC, out + OUT1);

    // agg_adj_lp (4 regions)
    agg_TL_k<<<dim3((NC + 255) / 256, NC), 256>>>(pC, pMuC, pIsC, gamma_c, beta_c, pDx1, pDy1, out);
    agg_TR_k<<<dim3((ND + 255) / 256, NC), 256>>>(adj, pDx1, pDy1, out);
    agg_BL_k<<<dim3((NC + 255) / 256, ND), 256>>>(pAdjT, pDx1, pDy1, out);
    agg_BR_k<<<dim3((ND + 255) / 256, ND), 256>>>(pD, pMuD, pIsD, gamma_d, beta_d, pDx1, pDy1, out);
}

// round 4
// speedup vs baseline: 1.9926x; 1.9926x over previous
#include <cuda_runtime.h>
#include <cuda_bf16.h>
#include <cstdint>

#define NC 4000
#define ND 2000
#define FC 2048
#define FD 1024
#define NT 6000

// output region offsets (floats)
#define OUT0 ((size_t)0)         // agg_cell_lp [4000,2000]
#define OUT1 ((size_t)8000000)   // agg_drug_lp [2000,4000]
#define OUT2 ((size_t)16000000)  // agg_adj_lp  [6000,6000]
#define OUT3 ((size_t)52000000)  // self_cell_lp diag [4000,4000]
#define OUT4 ((size_t)68000000)  // self_drug_lp diag [2000,2000]
#define OUT5 ((size_t)72000000)  // self_adj_lp  diag [6000,6000]

// scratch layout (float units)
#define S_C        ((size_t)0)          // 16,000,000  C_lin [4000,4000]
#define S_D        ((size_t)16000000)   //  4,000,000  D_lin [2000,2000]
#define S_ADJT     ((size_t)20000000)   //  8,000,000  adj^T [2000,4000]
#define S_A3C      ((size_t)28000000)   // 12,288,000  (bf16 [4000,6144])
#define S_B3C      ((size_t)40288000)   // 12,288,000  (bf16 [4000,6144])
#define S_A3D      ((size_t)52576000)   //  3,072,000  (bf16 [2000,3072])
#define S_B3D      ((size_t)55648000)   //  3,072,000  (bf16 [2000,3072])
#define S_PSUM     ((size_t)58720000)   //    128,000
#define S_PSQ      ((size_t)58848000)   //    128,000
#define S_RSADJ    ((size_t)58976000)   // 4000
#define S_CSADJ    ((size_t)58980000)   // 2000
#define S_MUC      ((size_t)58982000)   // 4000
#define S_ISC      ((size_t)58986000)   // 4000
#define S_MUD      ((size_t)58990000)   // 2000
#define S_ISD      ((size_t)58992000)   // 2000
#define S_RSC      ((size_t)58994000)   // 4000
#define S_RSD      ((size_t)58998000)   // 2000
#define S_DX       ((size_t)59000000)   // 4000
#define S_DY       ((size_t)59004000)   // 2000
#define S_DX1      ((size_t)59006000)   // 6000
#define S_DY1      ((size_t)59012000)   // 6000
#define S_TOTAL    ((size_t)59018000)

__device__ __align__(256) float g_scratch[S_TOTAL];

// ---------------------------------------------------------------------------
// zero a float region
// ---------------------------------------------------------------------------
__global__ void memzero_k(float* __restrict__ p, size_t n4)
{
    size_t i = (size_t)blockIdx.x * blockDim.x + threadIdx.x;
    if (i < n4) {
        float4 z = make_float4(0.f, 0.f, 0.f, 0.f);
        reinterpret_cast<float4*>(p)[i] = z;
    }
}

// ---------------------------------------------------------------------------
// split fp32 -> bf16 hi/lo, packed along K into 3 segments.
// mode 0 (A operand): [hi | hi | lo]
// mode 1 (B operand): [hi | lo | hi]
// ---------------------------------------------------------------------------
__global__ void split3_k(const float* __restrict__ in, __nv_bfloat16* __restrict__ out,
                         int rows, int K, int mode)
{
    size_t i = (size_t)blockIdx.x * blockDim.x + threadIdx.x;
    size_t total = (size_t)rows * K;
    if (i >= total) return;
    int r = (int)(i / K);
    int k = (int)(i % K);
    float x = in[i];
    __nv_bfloat16 hi = __float2bfloat16(x);
    __nv_bfloat16 lo = __float2bfloat16(x - __bfloat162float(hi));
    __nv_bfloat16* o = out + (size_t)r * 3 * K;
    o[k] = hi;
    if (mode == 0) { o[K + k] = hi; o[2 * K + k] = lo; }
    else           { o[K + k] = lo; o[2 * K + k] = hi; }
}

// ---------------------------------------------------------------------------
// bf16 NT tensor-core GEMM: C[m,n] = sum_k A[m,k]*B[n,k], fp32 accum.
// 128x128 tile, 8 warps (2x4), warp tile 64x32 via mma.m16n8k16.
// K-tile 32, cp.async double buffer, smem row stride 40 bf16 (80B).
// ---------------------------------------------------------------------------
__device__ __forceinline__ void load_tile_bf16(
    const __nv_bfloat16* __restrict__ G, int gRowBase, int nRows, int K, int k0,
    uint32_t sbase, int tid)
{
#pragma unroll
    for (int i = 0; i < 2; i++) {
        int ch  = tid + i * 256;       // 0..511
        int row = ch >> 2;             // 0..127
        int c16 = ch & 3;              // 16B chunk within 64B of row data
        uint32_t sa = sbase + (uint32_t)(row * 80 + c16 * 16);
        int gr = gRowBase + row;
        if (gr < nRows) {
            const void* gp = G + (size_t)gr * K + k0 + c16 * 8;
            asm volatile("cp.async.cg.shared.global [%0], [%1], 16;" :: "r"(sa), "l"(gp));
        } else {
            asm volatile("st.shared.v4.b32 [%0], {%1,%1,%1,%1};" :: "r"(sa), "r"(0u));
        }
    }
}

__global__ __launch_bounds__(256, 2) void gemm_bf16_nt(
    const __nv_bfloat16* __restrict__ A, const __nv_bfloat16* __restrict__ B,
    float* __restrict__ C, int M, int N, int K)
{
    __shared__ __nv_bfloat16 sA[2][128 * 40];
    __shared__ __nv_bfloat16 sB[2][128 * 40];

    const int tid  = threadIdx.x;
    const int lane = tid & 31;
    const int wid  = tid >> 5;
    const int wm   = wid >> 2;   // 0..1
    const int wn   = wid & 3;    // 0..3
    const int bm   = blockIdx.y * 128;
    const int bn   = blockIdx.x * 128;

    uint32_t aBase[2];
    uint32_t bBase[2];
    aBase[0] = (uint32_t)__cvta_generic_to_shared(sA[0]);
    aBase[1] = (uint32_t)__cvta_generic_to_shared(sA[1]);
    bBase[0] = (uint32_t)__cvta_generic_to_shared(sB[0]);
    bBase[1] = (uint32_t)__cvta_generic_to_shared(sB[1]);

    float d[4][4][4];
#pragma unroll
    for (int a = 0; a < 4; a++)
#pragma unroll
        for (int b = 0; b < 4; b++)
#pragma unroll
            for (int c = 0; c < 4; c++) d[a][b][c] = 0.0f;

    const int ntiles = K / 32;

    load_tile_bf16(A, bm, M, K, 0, aBase[0], tid);
    load_tile_bf16(B, bn, N, K, 0, bBase[0], tid);
    asm volatile("cp.async.commit_group;");
    asm volatile("cp.async.wait_group 0;");
    __syncthreads();

    // lane-level smem rows for ldmatrix
    const int arow = wm * 64 + (lane & 15);                       // within A tile
    const int brow = wn * 32 + ((lane & 16) >> 1) + (lane & 7);   // within B tile

    for (int kt = 0; kt < ntiles; kt++) {
        int buf = kt & 1;
        if (kt + 1 < ntiles) {
            load_tile_bf16(A, bm, M, K, (kt + 1) * 32, aBase[buf ^ 1], tid);
            load_tile_bf16(B, bn, N, K, (kt + 1) * 32, bBase[buf ^ 1], tid);
            asm volatile("cp.async.commit_group;");
        }

#pragma unroll
        for (int h = 0; h < 2; h++) {  // two k16 halves of the 32-wide K tile
            const int ac16 = h * 2 + (lane >> 4);
            uint32_t av[4][4];
#pragma unroll
            for (int mf = 0; mf < 4; mf++) {
                uint32_t aaddr = aBase[buf] + (uint32_t)((arow + mf * 16) * 80 + ac16 * 16);
                asm volatile("ldmatrix.sync.aligned.m8n8.x4.shared.b16 {%0,%1,%2,%3}, [%4];"
                             : "=r"(av[mf][0]), "=r"(av[mf][1]), "=r"(av[mf][2]), "=r"(av[mf][3])
                             : "r"(aaddr));
            }
            const int bc16 = h * 2 + ((lane >> 3) & 1);
            uint32_t bv[4][2];
#pragma unroll
            for (int np = 0; np < 2; np++) {
                uint32_t baddr = bBase[buf] + (uint32_t)((brow + np * 16) * 80 + bc16 * 16);
                uint32_t q0, q1, q2, q3;
                asm volatile("ldmatrix.sync.aligned.m8n8.x4.shared.b16 {%0,%1,%2,%3}, [%4];"
                             : "=r"(q0), "=r"(q1), "=r"(q2), "=r"(q3) : "r"(baddr));
                bv[np * 2][0] = q0;     bv[np * 2][1] = q1;
                bv[np * 2 + 1][0] = q2; bv[np * 2 + 1][1] = q3;
            }
#pragma unroll
            for (int mf = 0; mf < 4; mf++)
#pragma unroll
                for (int nf = 0; nf < 4; nf++)
                    asm volatile(
                        "mma.sync.aligned.m16n8k16.row.col.f32.bf16.bf16.f32 "
                        "{%0,%1,%2,%3}, {%4,%5,%6,%7}, {%8,%9}, {%0,%1,%2,%3};"
                        : "+f"(d[mf][nf][0]), "+f"(d[mf][nf][1]),
                          "+f"(d[mf][nf][2]), "+f"(d[mf][nf][3])
                        : "r"(av[mf][0]), "r"(av[mf][1]), "r"(av[mf][2]), "r"(av[mf][3]),
                          "r"(bv[nf][0]), "r"(bv[nf][1]));
        }

        if (kt + 1 < ntiles) asm volatile("cp.async.wait_group 0;");
        __syncthreads();
    }

    // epilogue
    const int er = bm + wm * 64 + (lane >> 2);
    const int ec = bn + wn * 32 + (lane & 3) * 2;
#pragma unroll
    for (int mf = 0; mf < 4; mf++) {
#pragma unroll
        for (int nf = 0; nf < 4; nf++) {
            int r = er + mf * 16, c = ec + nf * 8;
            if (c < N) {
                if (r < M)
                    *reinterpret_cast<float2*>(C + (size_t)r * N + c) =
                        make_float2(d[mf][nf][0], d[mf][nf][1]);
                if (r + 8 < M)
                    *reinterpret_cast<float2*>(C + (size_t)(r + 8) * N + c) =
                        make_float2(d[mf][nf][2], d[mf][nf][3]);
            }
        }
    }
}

// ---------------------------------------------------------------------------
// row reduce: out[row] = sum_j M[row,j]
// ---------------------------------------------------------------------------
__global__ void rowreduce_k(const float* __restrict__ Mp, int ncols, float* __restrict__ out)
{
    int row = blockIdx.x;
    const float* p = Mp + (size_t)row * ncols;
    float s = 0.0f;
    for (int j = threadIdx.x; j < ncols; j += blockDim.x) s += p[j];
    __shared__ float sh[256];
    sh[threadIdx.x] = s;
    __syncthreads();
    for (int st = 128; st > 0; st >>= 1) {
        if (threadIdx.x < st) sh[threadIdx.x] += sh[threadIdx.x + st];
        __syncthreads();
    }
    if (threadIdx.x == 0) out[row] = sh[0];
}

__global__ void rowsum_bn_k(const float* __restrict__ Mp, int ncols,
                            const float* __restrict__ gamma, const float* __restrict__ isd,
                            const float* __restrict__ mu, const float* __restrict__ beta,
                            float* __restrict__ out)
{
    int row = blockIdx.x;
    const float* p = Mp + (size_t)row * ncols;
    float s = 0.0f;
    for (int j = threadIdx.x; j < ncols; j += blockDim.x)
        s += gamma[j] * isd[j] * (p[j] - mu[j]) + beta[j];
    __shared__ float sh[256];
    sh[threadIdx.x] = s;
    __syncthreads();
    for (int st = 128; st > 0; st >>= 1) {
        if (threadIdx.x < st) sh[threadIdx.x] += sh[threadIdx.x + st];
        __syncthreads();
    }
    if (threadIdx.x == 0) out[row] = sh[0];
}

// ---------------------------------------------------------------------------
// column partial sums + sumsq (deterministic, fixed split)
// ---------------------------------------------------------------------------
__global__ void colstats_partial_k(const float* __restrict__ Mp, int nrows, int ncols,
                                   int rowsPerBlock, float* __restrict__ psum,
                                   float* __restrict__ psq)
{
    int j = blockIdx.x * blockDim.x + threadIdx.x;
    if (j >= ncols) return;
    int r0 = blockIdx.y * rowsPerBlock;
    int r1 = min(r0 + rowsPerBlock, nrows);
    float s = 0.0f, q = 0.0f;
    for (int i = r0; i < r1; i++) {
        float v = Mp[(size_t)i * ncols + j];
        s += v;
        q += v * v;
    }
    psum[(size_t)blockIdx.y * ncols + j] = s;
    psq [(size_t)blockIdx.y * ncols + j] = q;
}

__global__ void colstats_final_k(int nparts, int ncols, int nrows,
                                 const float* __restrict__ psum, const float* __restrict__ psq,
                                 float* __restrict__ mu, float* __restrict__ isd)
{
    int j = blockIdx.x * blockDim.x + threadIdx.x;
    if (j >= ncols) return;
    float s = 0.0f, q = 0.0f;
    for (int p = 0; p < nparts; p++) {
        s += psum[(size_t)p * ncols + j];
        q += psq [(size_t)p * ncols + j];
    }
    float m = s / (float)nrows;
    float var = q / (float)nrows - m * m;
    mu[j] = m;
    isd[j] = rsqrtf(var + 1e-5f);
}

__global__ void colsum_final_k(int nparts, int ncols, const float* __restrict__ psum,
                               float* __restrict__ out)
{
    int j = blockIdx.x * blockDim.x + threadIdx.x;
    if (j >= ncols) return;
    float s = 0.0f;
    for (int p = 0; p < nparts; p++) s += psum[(size_t)p * ncols + j];
    out[j] = s;
}

// ---------------------------------------------------------------------------
// transpose adj [4000,2000] -> adjT [2000,4000]
// ---------------------------------------------------------------------------
__global__ void transpose_k(const float* __restrict__ in, float* __restrict__ out,
                            int rows, int cols)
{
    __shared__ float tile[32][33];
    int c = blockIdx.x * 32 + threadIdx.x;
    int r = blockIdx.y * 32 + threadIdx.y;
#pragma unroll
    for (int i = 0; i < 32; i += 8)
        if (r + i < rows && c < cols)
            tile[threadIdx.y + i][threadIdx.x] = in[(size_t)(r + i) * cols + c];
    __syncthreads();
    int oc = blockIdx.y * 32 + threadIdx.x;
    int orow = blockIdx.x * 32 + threadIdx.y;
#pragma unroll
    for (int i = 0; i < 32; i += 8)
        if (orow + i < cols && oc < rows)
            out[(size_t)(orow + i) * rows + oc] = tile[threadIdx.x][threadIdx.y + i];
}

// ---------------------------------------------------------------------------
// finalize scalar vectors + diag writes
// ---------------------------------------------------------------------------
__global__ void finalize_k(const float* __restrict__ beta_c, const float* __restrict__ beta_d,
                           const float* __restrict__ rs_adj, const float* __restrict__ cs_adj,
                           const float* __restrict__ rs_c, const float* __restrict__ rs_d,
                           float* __restrict__ dx, float* __restrict__ dy,
                           float* __restrict__ dx1, float* __restrict__ dy1,
                           float* __restrict__ out)
{
    int r = blockIdx.x * blockDim.x + threadIdx.x;
    if (r >= NT) return;
    float rsA, csA;
    if (r < NC) {
        float ra = rs_adj[r];
        dx[r] = rsqrtf(ra + 1.0f);
        rsA = rs_c[r] + ra;
        csA = (float)NC * beta_c[r] + ra;   // colsum of BN'd cell = n*beta
    } else {
        int d = r - NC;
        float ca = cs_adj[d];
        dy[d] = rsqrtf(ca + 1.0f);
        rsA = ca + rs_d[d];
        csA = ca + (float)ND * beta_d[d];
    }
    dx1[r] = rsqrtf(rsA + 1.0f);
    dy1[r] = rsqrtf(csA + 1.0f);
    float dval = 1.0f / (rsA + 1.0f) + 1.0f;
    out[OUT5 + (size_t)r * (NT + 1)] = dval;
    if (r < NC) out[OUT3 + (size_t)r * (NC + 1)] = dval;
    else        out[OUT4 + (size_t)(r - NC) * (ND + 1)] = dval;
}

// ---------------------------------------------------------------------------
// output assembly kernels
// ---------------------------------------------------------------------------
__global__ void scale_mat_k(const float* __restrict__ m, const float* __restrict__ dr,
                            const float* __restrict__ dc, int cols,
                            float* __restrict__ out)
{
    int j = blockIdx.x * blockDim.x + threadIdx.x;
    int i = blockIdx.y;
    if (j < cols)
        out[(size_t)i * cols + j] = dr[i] * m[(size_t)i * cols + j] * dc[j];
}

__global__ void agg_TL_k(const float* __restrict__ Cm, const float* __restrict__ mu,
                         const float* __restrict__ isd, const float* __restrict__ gamma,
                         const float* __restrict__ beta, const float* __restrict__ dx1,
                         const float* __restrict__ dy1, float* __restrict__ out)
{
    int j = blockIdx.x * blockDim.x + threadIdx.x;
    int r = blockIdx.y;
    if (j >= NC) return;
    float v = gamma[j] * (Cm[(size_t)r * NC + j] - mu[j]) * isd[j] + beta[j];
    out[OUT2 + (size_t)r * NT + j] = dx1[r] * dy1[j] * v;
}

__global__ void agg_TR_k(const float* __restrict__ adj, const float* __restrict__ dx1,
                         const float* __restrict__ dy1, float* __restrict__ out)
{
    int j = blockIdx.x * blockDim.x + threadIdx.x;
    int r = blockIdx.y;
    if (j >= ND) return;
    out[OUT2 + (size_t)r * NT + NC + j] = dx1[r] * dy1[NC + j] * adj[(size_t)r * ND + j];
}

__global__ void agg_BL_k(const float* __restrict__ adjT, const float* __restrict__ dx1,
                         const float* __restrict__ dy1, float* __restrict__ out)
{
    int j = blockIdx.x * blockDim.x + threadIdx.x;
    int d = blockIdx.y;
    if (j >= NC) return;
    out[OUT2 + (size_t)(NC + d) * NT + j] = dx1[NC + d] * dy1[j] * adjT[(size_t)d * NC + j];
}

__global__ void agg_BR_k(const float* __restrict__ Dm, const float* __restrict__ mu,
                         const float* __restrict__ isd, const float* __restrict__ gamma,
                         const float* __restrict__ beta, const float* __restrict__ dx1,
                         const float* __restrict__ dy1, float* __restrict__ out)
{
    int j = blockIdx.x * blockDim.x + threadIdx.x;
    int d = blockIdx.y;
    if (j >= ND) return;
    float v = gamma[j] * (Dm[(size_t)d * ND + j] - mu[j]) * isd[j] + beta[j];
    out[OUT2 + (size_t)(NC + d) * NT + NC + j] = dx1[NC + d] * dy1[NC + j] * v;
}

// ---------------------------------------------------------------------------
extern "C" void kernel_launch(void* const* d_in, const int* in_sizes, int n_in,
                              void* d_out, int out_size)
{
    const float* adj       = (const float*)d_in[0];
    const float* cell_feat = (const float*)d_in[1];
    const float* drug_feat = (const float*)d_in[2];
    const float* W_cell    = (const float*)d_in[3];
    const float* W_drug    = (const float*)d_in[5];
    const float* gamma_c   = (const float*)d_in[7];
    const float* beta_c    = (const float*)d_in[8];
    const float* gamma_d   = (const float*)d_in[9];
    const float* beta_d    = (const float*)d_in[10];
    float* out = (float*)d_out;

    float* sc = nullptr;
    cudaGetSymbolAddress((void**)&sc, g_scratch);

    float* pC     = sc + S_C;
    float* pD     = sc + S_D;
    float* pAdjT  = sc + S_ADJT;
    __nv_bfloat16* pA3C = (__nv_bfloat16*)(sc + S_A3C);
    __nv_bfloat16* pB3C = (__nv_bfloat16*)(sc + S_B3C);
    __nv_bfloat16* pA3D = (__nv_bfloat16*)(sc + S_A3D);
    __nv_bfloat16* pB3D = (__nv_bfloat16*)(sc + S_B3D);
    float* pPsum  = sc + S_PSUM;
    float* pPsq   = sc + S_PSQ;
    float* pRsAdj = sc + S_RSADJ;
    float* pCsAdj = sc + S_CSADJ;
    float* pMuC   = sc + S_MUC;
    float* pIsC   = sc + S_ISC;
    float* pMuD   = sc + S_MUD;
    float* pIsD   = sc + S_ISD;
    float* pRsC   = sc + S_RSC;
    float* pRsD   = sc + S_RSD;
    float* pDx    = sc + S_DX;
    float* pDy    = sc + S_DY;
    float* pDx1   = sc + S_DX1;
    float* pDy1   = sc + S_DY1;

    // zero diag output regions
    {
        size_t n3 = ((size_t)NC * NC) / 4, n4 = ((size_t)ND * ND) / 4, n5 = ((size_t)NT * NT) / 4;
        memzero_k<<<(unsigned)((n3 + 255) / 256), 256>>>(out + OUT3, n3);
        memzero_k<<<(unsigned)((n4 + 255) / 256), 256>>>(out + OUT4, n4);
        memzero_k<<<(unsigned)((n5 + 255) / 256), 256>>>(out + OUT5, n5);
    }

    // adj reductions + transpose
    rowreduce_k<<<NC, 256>>>(adj, ND, pRsAdj);
    colstats_partial_k<<<dim3((ND + 255) / 256, 16), 256>>>(adj, NC, ND, 250, pPsum, pPsq);
    colsum_final_k<<<(ND + 255) / 256, 256>>>(16, ND, pPsum, pCsAdj);
    transpose_k<<<dim3((ND + 31) / 32, (NC + 31) / 32), dim3(32, 8)>>>(adj, pAdjT, NC, ND);

    // split-bf16 packing (A: [hi|hi|lo], B: [hi|lo|hi])
    {
        size_t tc = (size_t)NC * FC;  // 8.192M
        split3_k<<<(unsigned)((tc + 255) / 256), 256>>>(cell_feat, pA3C, NC, FC, 0);
        split3_k<<<(unsigned)((tc + 255) / 256), 256>>>(W_cell,    pB3C, NC, FC, 1);
        size_t td = (size_t)ND * FD;  // 2.048M
        split3_k<<<(unsigned)((td + 255) / 256), 256>>>(drug_feat, pA3D, ND, FD, 0);
        split3_k<<<(unsigned)((td + 255) / 256), 256>>>(W_drug,    pB3D, ND, FD, 1);
    }

    // cell GEMM (tensor cores, K'=3*2048=6144) + BN stats + BN rowsums
    gemm_bf16_nt<<<dim3(32, 32), 256>>>(pA3C, pB3C, pC, NC, NC, 3 * FC);
    colstats_partial_k<<<dim3((NC + 255) / 256, 20), 256>>>(pC, NC, NC, 200, pPsum, pPsq);
    colstats_final_k<<<(NC + 255) / 256, 256>>>(20, NC, NC, pPsum, pPsq, pMuC, pIsC);
    rowsum_bn_k<<<NC, 256>>>(pC, NC, gamma_c, pIsC, pMuC, beta_c, pRsC);

    // drug GEMM (K'=3*1024=3072) + BN stats + BN rowsums
    gemm_bf16_nt<<<dim3(16, 16), 256>>>(pA3D, pB3D, pD, ND, ND, 3 * FD);
    colstats_partial_k<<<dim3((ND + 255) / 256, 10), 256>>>(pD, ND, ND, 200, pPsum, pPsq);
    colstats_final_k<<<(ND + 255) / 256, 256>>>(10, ND, ND, pPsum, pPsq, pMuD, pIsD);
    rowsum_bn_k<<<ND, 256>>>(pD, ND, gamma_d, pIsD, pMuD, beta_d, pRsD);

    // scalars + diagonals
    finalize_k<<<(NT + 255) / 256, 256>>>(beta_c, beta_d, pRsAdj, pCsAdj, pRsC, pRsD,
                                          pDx, pDy, pDx1, pDy1, out);

    // agg_cell_lp / agg_drug_lp
    scale_mat_k<<<dim3((ND + 255) / 256, NC), 256>>>(adj, pDx, pDy, ND, out + OUT0);
    scale_mat_k<<<dim3((NC + 255) / 256, ND), 256>>>(pAdjT, pDy, pDx, NC, out + OUT1);

    // agg_adj_lp (4 regions)
    agg_TL_k<<<dim3((NC + 255) / 256, NC), 256>>>(pC, pMuC, pIsC, gamma_c, beta_c, pDx1, pDy1, out);
    agg_TR_k<<<dim3((ND + 255) / 256, NC), 256>>>(adj, pDx1, pDy1, out);
    agg_BL_k<<<dim3((NC + 255) / 256, ND), 256>>>(pAdjT, pDx1, pDy1, out);
    agg_BR_k<<<dim3((ND + 255) / 256, ND), 256>>>(pD, pMuD, pIsD, gamma_d, beta_d, pDx1, pDy1, out);
}

// round 6
// speedup vs baseline: 2.0606x; 1.0341x over previous
#include <cuda_runtime.h>
#include <cuda_bf16.h>
#include <cstdint>

#define NC 4000
#define ND 2000
#define FC 2048
#define FD 1024
#define NT 6000

// output region offsets (floats)
#define OUT0 ((size_t)0)         // agg_cell_lp [4000,2000]
#define OUT1 ((size_t)8000000)   // agg_drug_lp [2000,4000]
#define OUT2 ((size_t)16000000)  // agg_adj_lp  [6000,6000]
#define OUT3 ((size_t)52000000)  // self_cell_lp diag [4000,4000]
#define OUT4 ((size_t)68000000)  // self_drug_lp diag [2000,2000]
#define OUT5 ((size_t)72000000)  // self_adj_lp  diag [6000,6000]

// scratch layout (float units); bf16 operands padded to 4096/2048 rows (pads stay 0)
#define S_C        ((size_t)0)           // 16,000,000  C_lin [4000,4000]
#define S_D        ((size_t)16000000)    //  4,000,000  D_lin [2000,2000]
#define S_ADJT     ((size_t)20000000)    //  8,000,000  adj^T [2000,4000]
#define S_A3C      ((size_t)28000000)    // bf16 [4096,6144] = 12,582,912 fl
#define S_B3C      ((size_t)40582912)    // bf16 [4096,6144]
#define S_A3D      ((size_t)53165824)    // bf16 [2048,3072] = 3,145,728 fl
#define S_B3D      ((size_t)56311552)    // bf16 [2048,3072]
#define S_PSUM     ((size_t)59457280)    // 128,000
#define S_PSQ      ((size_t)59585280)    // 128,000
#define S_RSADJ    ((size_t)59713280)    // 4000
#define S_CSADJ    ((size_t)59717280)    // 2000
#define S_MUC      ((size_t)59719280)    // 4000
#define S_ISC      ((size_t)59723280)    // 4000
#define S_MUD      ((size_t)59727280)    // 2000
#define S_ISD      ((size_t)59729280)    // 2000
#define S_RSC      ((size_t)59731280)    // 4000
#define S_RSD      ((size_t)59735280)    // 2000
#define S_DX       ((size_t)59737280)    // 4000
#define S_DY       ((size_t)59741280)    // 2000
#define S_DX1      ((size_t)59743280)    // 6000
#define S_DY1      ((size_t)59749280)    // 6000
#define S_TOTAL    ((size_t)59755280)

__device__ __align__(256) float g_scratch[S_TOTAL];

// GEMM smem: 4 stages x (A 128x32 + B 128x32, 80B row stride) = 4 x 20480
#define STG 20480
#define GEMM_SMEM_DYN (4 * STG)

// ---------------------------------------------------------------------------
// zero a float region
// ---------------------------------------------------------------------------
__global__ void memzero_k(float* __restrict__ p, size_t n4)
{
    size_t i = (size_t)blockIdx.x * blockDim.x + threadIdx.x;
    if (i < n4) {
        float4 z = make_float4(0.f, 0.f, 0.f, 0.f);
        reinterpret_cast<float4*>(p)[i] = z;
    }
}

// ---------------------------------------------------------------------------
// split fp32 -> bf16 hi/lo packed along K into 3 segments.
// mode 0 (A operand): [hi | hi | lo]; mode 1 (B operand): [hi | lo | hi]
// ---------------------------------------------------------------------------
__global__ void split3_k(const float* __restrict__ in, __nv_bfloat16* __restrict__ out,
                         int rows, int K, int mode)
{
    size_t i = (size_t)blockIdx.x * blockDim.x + threadIdx.x;
    size_t total = (size_t)rows * K;
    if (i >= total) return;
    int r = (int)(i / K);
    int k = (int)(i % K);
    float x = in[i];
    __nv_bfloat16 hi = __float2bfloat16(x);
    __nv_bfloat16 lo = __float2bfloat16(x - __bfloat162float(hi));
    __nv_bfloat16* o = out + (size_t)r * 3 * K;
    o[k] = hi;
    if (mode == 0) { o[K + k] = hi; o[2 * K + k] = lo; }
    else           { o[K + k] = lo; o[2 * K + k] = hi; }
}

// ---------------------------------------------------------------------------
// bf16 NT tensor-core GEMM (mma.sync), 128x128 tile, 8 warps (2x4),
// warp tile 64x32 via m16n8k16, BK=32, 4-stage cp.async pipeline.
// Operands must be row-padded so no load guards are needed.
// ---------------------------------------------------------------------------
__device__ __forceinline__ void load_stage32(
    const __nv_bfloat16* __restrict__ A, const __nv_bfloat16* __restrict__ B,
    int bm, int bn, int K, int k0, uint32_t sbase, int tid)
{
    const __nv_bfloat16* ga = A + (size_t)bm * K + k0;
#pragma unroll
    for (int i = 0; i < 2; i++) {          // 128 rows x 4 chunks / 256 thr
        int u = tid + i * 256;
        int row = u >> 2, c = u & 3;
        uint32_t sa = sbase + (uint32_t)(row * 80 + c * 16);
        const void* gp = ga + (size_t)row * K + c * 8;
        asm volatile("cp.async.cg.shared.global [%0], [%1], 16;" :: "r"(sa), "l"(gp));
    }
    const __nv_bfloat16* gb = B + (size_t)bn * K + k0;
#pragma unroll
    for (int i = 0; i < 2; i++) {
        int u = tid + i * 256;
        int row = u >> 2, c = u & 3;
        uint32_t sa = sbase + (uint32_t)(10240 + row * 80 + c * 16);
        const void* gp = gb + (size_t)row * K + c * 8;
        asm volatile("cp.async.cg.shared.global [%0], [%1], 16;" :: "r"(sa), "l"(gp));
    }
}

__global__ __launch_bounds__(256, 2) void gemm_mma(
    const __nv_bfloat16* __restrict__ A, const __nv_bfloat16* __restrict__ B,
    float* __restrict__ C, int Mreal, int Nreal, int K)
{
    extern __shared__ __align__(128) char dsm[];

    const int tid  = threadIdx.x;
    const int lane = tid & 31;
    const int wid  = tid >> 5;
    const int wm   = wid >> 2;   // 0..1
    const int wn   = wid & 3;    // 0..3
    const int bm   = blockIdx.y * 128;
    const int bn   = blockIdx.x * 128;

    uint32_t base = (uint32_t)__cvta_generic_to_shared(dsm);

    float d[4][4][4];
#pragma unroll
    for (int a = 0; a < 4; a++)
#pragma unroll
        for (int b = 0; b < 4; b++)
#pragma unroll
            for (int c = 0; c < 4; c++) d[a][b][c] = 0.0f;

    const int S = K / 32;

    // prologue: preload 3 stages
#pragma unroll
    for (int p = 0; p < 3; p++) {
        load_stage32(A, B, bm, bn, K, p * 32, base + p * STG, tid);
        asm volatile("cp.async.commit_group;");
    }

    const int arow = wm * 64 + (lane & 15);
    const int brow = wn * 32 + ((lane & 16) >> 1) + (lane & 7);

    for (int s = 0; s < S; s++) {
        // ensure stage s has arrived (pending groups before wait = min(3, S-s))
        if (S - s >= 3)      asm volatile("cp.async.wait_group 2;");
        else if (S - s == 2) asm volatile("cp.async.wait_group 1;");
        else                 asm volatile("cp.async.wait_group 0;");
        __syncthreads();

        if (s + 3 < S) {
            load_stage32(A, B, bm, bn, K, (s + 3) * 32, base + ((s + 3) & 3) * STG, tid);
            asm volatile("cp.async.commit_group;");
        }

        uint32_t aB = base + (s & 3) * STG;
        uint32_t bB = aB + 10240;

#pragma unroll
        for (int h = 0; h < 2; h++) {  // two k16 halves of the 32-wide K tile
            const int ac16 = h * 2 + (lane >> 4);
            uint32_t av[4][4];
#pragma unroll
            for (int mf = 0; mf < 4; mf++) {
                uint32_t aaddr = aB + (uint32_t)((arow + mf * 16) * 80 + ac16 * 16);
                asm volatile("ldmatrix.sync.aligned.m8n8.x4.shared.b16 {%0,%1,%2,%3}, [%4];"
                             : "=r"(av[mf][0]), "=r"(av[mf][1]), "=r"(av[mf][2]), "=r"(av[mf][3])
                             : "r"(aaddr));
            }
            const int bc16 = h * 2 + ((lane >> 3) & 1);
            uint32_t bv[4][2];
#pragma unroll
            for (int np = 0; np < 2; np++) {
                uint32_t baddr = bB + (uint32_t)((brow + np * 16) * 80 + bc16 * 16);
                uint32_t q0, q1, q2, q3;
                asm volatile("ldmatrix.sync.aligned.m8n8.x4.shared.b16 {%0,%1,%2,%3}, [%4];"
                             : "=r"(q0), "=r"(q1), "=r"(q2), "=r"(q3) : "r"(baddr));
                bv[np * 2][0] = q0;     bv[np * 2][1] = q1;
                bv[np * 2 + 1][0] = q2; bv[np * 2 + 1][1] = q3;
            }
#pragma unroll
            for (int mf = 0; mf < 4; mf++)
#pragma unroll
                for (int nf = 0; nf < 4; nf++)
                    asm volatile(
                        "mma.sync.aligned.m16n8k16.row.col.f32.bf16.bf16.f32 "
                        "{%0,%1,%2,%3}, {%4,%5,%6,%7}, {%8,%9}, {%0,%1,%2,%3};"
                        : "+f"(d[mf][nf][0]), "+f"(d[mf][nf][1]),
                          "+f"(d[mf][nf][2]), "+f"(d[mf][nf][3])
                        : "r"(av[mf][0]), "r"(av[mf][1]), "r"(av[mf][2]), "r"(av[mf][3]),
                          "r"(bv[nf][0]), "r"(bv[nf][1]));
        }
    }

    // epilogue
    const int er = bm + wm * 64 + (lane >> 2);
    const int ec = bn + wn * 32 + (lane & 3) * 2;
#pragma unroll
    for (int mf = 0; mf < 4; mf++) {
#pragma unroll
        for (int nf = 0; nf < 4; nf++) {
            int r = er + mf * 16, c = ec + nf * 8;
            if (c < Nreal) {
                if (r < Mreal)
                    *reinterpret_cast<float2*>(C + (size_t)r * Nreal + c) =
                        make_float2(d[mf][nf][0], d[mf][nf][1]);
                if (r + 8 < Mreal)
                    *reinterpret_cast<float2*>(C + (size_t)(r + 8) * Nreal + c) =
                        make_float2(d[mf][nf][2], d[mf][nf][3]);
            }
        }
    }
}

// ---------------------------------------------------------------------------
// row reduce: out[row] = sum_j M[row,j]
// ---------------------------------------------------------------------------
__global__ void rowreduce_k(const float* __restrict__ Mp, int ncols, float* __restrict__ out)
{
    int row = blockIdx.x;
    const float* p = Mp + (size_t)row * ncols;
    float s = 0.0f;
    for (int j = threadIdx.x; j < ncols; j += blockDim.x) s += p[j];
    __shared__ float sh[256];
    sh[threadIdx.x] = s;
    __syncthreads();
    for (int st = 128; st > 0; st >>= 1) {
        if (threadIdx.x < st) sh[threadIdx.x] += sh[threadIdx.x + st];
        __syncthreads();
    }
    if (threadIdx.x == 0) out[row] = sh[0];
}

__global__ void rowsum_bn_k(const float* __restrict__ Mp, int ncols,
                            const float* __restrict__ gamma, const float* __restrict__ isd,
                            const float* __restrict__ mu, const float* __restrict__ beta,
                            float* __restrict__ out)
{
    int row = blockIdx.x;
    const float* p = Mp + (size_t)row * ncols;
    float s = 0.0f;
    for (int j = threadIdx.x; j < ncols; j += blockDim.x)
        s += gamma[j] * isd[j] * (p[j] - mu[j]) + beta[j];
    __shared__ float sh[256];
    sh[threadIdx.x] = s;
    __syncthreads();
    for (int st = 128; st > 0; st >>= 1) {
        if (threadIdx.x < st) sh[threadIdx.x] += sh[threadIdx.x + st];
        __syncthreads();
    }
    if (threadIdx.x == 0) out[row] = sh[0];
}

// ---------------------------------------------------------------------------
// column partial sums + sumsq (deterministic, fixed split)
// ---------------------------------------------------------------------------
__global__ void colstats_partial_k(const float* __restrict__ Mp, int nrows, int ncols,
                                   int rowsPerBlock, float* __restrict__ psum,
                                   float* __restrict__ psq)
{
    int j = blockIdx.x * blockDim.x + threadIdx.x;
    if (j >= ncols) return;
    int r0 = blockIdx.y * rowsPerBlock;
    int r1 = min(r0 + rowsPerBlock, nrows);
    float s = 0.0f, q = 0.0f;
    for (int i = r0; i < r1; i++) {
        float v = Mp[(size_t)i * ncols + j];
        s += v;
        q += v * v;
    }
    psum[(size_t)blockIdx.y * ncols + j] = s;
    psq [(size_t)blockIdx.y * ncols + j] = q;
}

__global__ void colstats_final_k(int nparts, int ncols, int nrows,
                                 const float* __restrict__ psum, const float* __restrict__ psq,
                                 float* __restrict__ mu, float* __restrict__ isd)
{
    int j = blockIdx.x * blockDim.x + threadIdx.x;
    if (j >= ncols) return;
    float s = 0.0f, q = 0.0f;
    for (int p = 0; p < nparts; p++) {
        s += psum[(size_t)p * ncols + j];
        q += psq [(size_t)p * ncols + j];
    }
    float m = s / (float)nrows;
    float var = q / (float)nrows - m * m;
    mu[j] = m;
    isd[j] = rsqrtf(var + 1e-5f);
}

__global__ void colsum_final_k(int nparts, int ncols, const float* __restrict__ psum,
                               float* __restrict__ out)
{
    int j = blockIdx.x * blockDim.x + threadIdx.x;
    if (j >= ncols) return;
    float s = 0.0f;
    for (int p = 0; p < nparts; p++) s += psum[(size_t)p * ncols + j];
    out[j] = s;
}

// ---------------------------------------------------------------------------
// transpose adj [4000,2000] -> adjT [2000,4000]
// ---------------------------------------------------------------------------
__global__ void transpose_k(const float* __restrict__ in, float* __restrict__ out,
                            int rows, int cols)
{
    __shared__ float tile[32][33];
    int c = blockIdx.x * 32 + threadIdx.x;
    int r = blockIdx.y * 32 + threadIdx.y;
#pragma unroll
    for (int i = 0; i < 32; i += 8)
        if (r + i < rows && c < cols)
            tile[threadIdx.y + i][threadIdx.x] = in[(size_t)(r + i) * cols + c];
    __syncthreads();
    int oc = blockIdx.y * 32 + threadIdx.x;
    int orow = blockIdx.x * 32 + threadIdx.y;
#pragma unroll
    for (int i = 0; i < 32; i += 8)
        if (orow + i < cols && oc < rows)
            out[(size_t)(orow + i) * rows + oc] = tile[threadIdx.x][threadIdx.y + i];
}

// ---------------------------------------------------------------------------
// finalize scalar vectors + diag writes
// ---------------------------------------------------------------------------
__global__ void finalize_k(const float* __restrict__ beta_c, const float* __restrict__ beta_d,
                           const float* __restrict__ rs_adj, const float* __restrict__ cs_adj,
                           const float* __restrict__ rs_c, const float* __restrict__ rs_d,
                           float* __restrict__ dx, float* __restrict__ dy,
                           float* __restrict__ dx1, float* __restrict__ dy1,
                           float* __restrict__ out)
{
    int r = blockIdx.x * blockDim.x + threadIdx.x;
    if (r >= NT) return;
    float rsA, csA;
    if (r < NC) {
        float ra = rs_adj[r];
        dx[r] = rsqrtf(ra + 1.0f);
        rsA = rs_c[r] + ra;
        csA = (float)NC * beta_c[r] + ra;   // colsum of BN'd cell = n*beta
    } else {
        int d = r - NC;
        float ca = cs_adj[d];
        dy[d] = rsqrtf(ca + 1.0f);
        rsA = ca + rs_d[d];
        csA = ca + (float)ND * beta_d[d];
    }
    dx1[r] = rsqrtf(rsA + 1.0f);
    dy1[r] = rsqrtf(csA + 1.0f);
    float dval = 1.0f / (rsA + 1.0f) + 1.0f;
    out[OUT5 + (size_t)r * (NT + 1)] = dval;
    if (r < NC) out[OUT3 + (size_t)r * (NC + 1)] = dval;
    else        out[OUT4 + (size_t)(r - NC) * (ND + 1)] = dval;
}

// ---------------------------------------------------------------------------
// output assembly kernels
// ---------------------------------------------------------------------------
__global__ void scale_mat_k(const float* __restrict__ m, const float* __restrict__ dr,
                            const float* __restrict__ dc, int cols,
                            float* __restrict__ out)
{
    int j = blockIdx.x * blockDim.x + threadIdx.x;
    int i = blockIdx.y;
    if (j < cols)
        out[(size_t)i * cols + j] = dr[i] * m[(size_t)i * cols + j] * dc[j];
}

__global__ void agg_TL_k(const float* __restrict__ Cm, const float* __restrict__ mu,
                         const float* __restrict__ isd, const float* __restrict__ gamma,
                         const float* __restrict__ beta, const float* __restrict__ dx1,
                         const float* __restrict__ dy1, float* __restrict__ out)
{
    int j = blockIdx.x * blockDim.x + threadIdx.x;
    int r = blockIdx.y;
    if (j >= NC) return;
    float v = gamma[j] * (Cm[(size_t)r * NC + j] - mu[j]) * isd[j] + beta[j];
    out[OUT2 + (size_t)r * NT + j] = dx1[r] * dy1[j] * v;
}

__global__ void agg_TR_k(const float* __restrict__ adj, const float* __restrict__ dx1,
                         const float* __restrict__ dy1, float* __restrict__ out)
{
    int j = blockIdx.x * blockDim.x + threadIdx.x;
    int r = blockIdx.y;
    if (j >= ND) return;
    out[OUT2 + (size_t)r * NT + NC + j] = dx1[r] * dy1[NC + j] * adj[(size_t)r * ND + j];
}

__global__ void agg_BL_k(const float* __restrict__ adjT, const float* __restrict__ dx1,
                         const float* __restrict__ dy1, float* __restrict__ out)
{
    int j = blockIdx.x * blockDim.x + threadIdx.x;
    int d = blockIdx.y;
    if (j >= NC) return;
    out[OUT2 + (size_t)(NC + d) * NT + j] = dx1[NC + d] * dy1[j] * adjT[(size_t)d * NC + j];
}

__global__ void agg_BR_k(const float* __restrict__ Dm, const float* __restrict__ mu,
                         const float* __restrict__ isd, const float* __restrict__ gamma,
                         const float* __restrict__ beta, const float* __restrict__ dx1,
                         const float* __restrict__ dy1, float* __restrict__ out)
{
    int j = blockIdx.x * blockDim.x + threadIdx.x;
    int d = blockIdx.y;
    if (j >= ND) return;
    float v = gamma[j] * (Dm[(size_t)d * ND + j] - mu[j]) * isd[j] + beta[j];
    out[OUT2 + (size_t)(NC + d) * NT + NC + j] = dx1[NC + d] * dy1[NC + j] * v;
}

// ---------------------------------------------------------------------------
extern "C" void kernel_launch(void* const* d_in, const int* in_sizes, int n_in,
                              void* d_out, int out_size)
{
    const float* adj       = (const float*)d_in[0];
    const float* cell_feat = (const float*)d_in[1];
    const float* drug_feat = (const float*)d_in[2];
    const float* W_cell    = (const float*)d_in[3];
    const float* W_drug    = (const float*)d_in[5];
    const float* gamma_c   = (const float*)d_in[7];
    const float* beta_c    = (const float*)d_in[8];
    const float* gamma_d   = (const float*)d_in[9];
    const float* beta_d    = (const float*)d_in[10];
    float* out = (float*)d_out;

    float* sc = nullptr;
    cudaGetSymbolAddress((void**)&sc, g_scratch);
    cudaFuncSetAttribute(gemm_mma, cudaFuncAttributeMaxDynamicSharedMemorySize, GEMM_SMEM_DYN);

    float* pC     = sc + S_C;
    float* pD     = sc + S_D;
    float* pAdjT  = sc + S_ADJT;
    __nv_bfloat16* pA3C = (__nv_bfloat16*)(sc + S_A3C);
    __nv_bfloat16* pB3C = (__nv_bfloat16*)(sc + S_B3C);
    __nv_bfloat16* pA3D = (__nv_bfloat16*)(sc + S_A3D);
    __nv_bfloat16* pB3D = (__nv_bfloat16*)(sc + S_B3D);
    float* pPsum  = sc + S_PSUM;
    float* pPsq   = sc + S_PSQ;
    float* pRsAdj = sc + S_RSADJ;
    float* pCsAdj = sc + S_CSADJ;
    float* pMuC   = sc + S_MUC;
    float* pIsC   = sc + S_ISC;
    float* pMuD   = sc + S_MUD;
    float* pIsD   = sc + S_ISD;
    float* pRsC   = sc + S_RSC;
    float* pRsD   = sc + S_RSD;
    float* pDx    = sc + S_DX;
    float* pDy    = sc + S_DY;
    float* pDx1   = sc + S_DX1;
    float* pDy1   = sc + S_DY1;

    // split-bf16 packing (A: [hi|hi|lo], B: [hi|lo|hi]); row pads stay zero.
    size_t tc = (size_t)NC * FC;
    size_t td = (size_t)ND * FD;
    split3_k<<<(unsigned)((tc + 255) / 256), 256>>>(cell_feat, pA3C, NC, FC, 0);  // launch 0
    split3_k<<<(unsigned)((tc + 255) / 256), 256>>>(W_cell,    pB3C, NC, FC, 1);  // launch 1
    split3_k<<<(unsigned)((td + 255) / 256), 256>>>(drug_feat, pA3D, ND, FD, 0);  // launch 2

    // cell GEMM at launch index 3 => ncu capture target
    gemm_mma<<<dim3(32, 32), 256, GEMM_SMEM_DYN>>>(pA3C, pB3C, pC, NC, NC, 3 * FC);

    split3_k<<<(unsigned)((td + 255) / 256), 256>>>(W_drug, pB3D, ND, FD, 1);
    gemm_mma<<<dim3(16, 16), 256, GEMM_SMEM_DYN>>>(pA3D, pB3D, pD, ND, ND, 3 * FD);

    // zero diag output regions
    {
        size_t n3 = ((size_t)NC * NC) / 4, n4 = ((size_t)ND * ND) / 4, n5 = ((size_t)NT * NT) / 4;
        memzero_k<<<(unsigned)((n3 + 255) / 256), 256>>>(out + OUT3, n3);
        memzero_k<<<(unsigned)((n4 + 255) / 256), 256>>>(out + OUT4, n4);
        memzero_k<<<(unsigned)((n5 + 255) / 256), 256>>>(out + OUT5, n5);
    }

    // adj reductions + transpose
    rowreduce_k<<<NC, 256>>>(adj, ND, pRsAdj);
    colstats_partial_k<<<dim3((ND + 255) / 256, 16), 256>>>(adj, NC, ND, 250, pPsum, pPsq);
    colsum_final_k<<<(ND + 255) / 256, 256>>>(16, ND, pPsum, pCsAdj);
    transpose_k<<<dim3((ND + 31) / 32, (NC + 31) / 32), dim3(32, 8)>>>(adj, pAdjT, NC, ND);

    // BN stats + BN rowsums
    colstats_partial_k<<<dim3((NC + 255) / 256, 20), 256>>>(pC, NC, NC, 200, pPsum, pPsq);
    colstats_final_k<<<(NC + 255) / 256, 256>>>(20, NC, NC, pPsum, pPsq, pMuC, pIsC);
    rowsum_bn_k<<<NC, 256>>>(pC, NC, gamma_c, pIsC, pMuC, beta_c, pRsC);

    colstats_partial_k<<<dim3((ND + 255) / 256, 10), 256>>>(pD, ND, ND, 200, pPsum, pPsq);
    colstats_final_k<<<(ND + 255) / 256, 256>>>(10, ND, ND, pPsum, pPsq, pMuD, pIsD);
    rowsum_bn_k<<<ND, 256>>>(pD, ND, gamma_d, pIsD, pMuD, beta_d, pRsD);

    // scalars + diagonals
    finalize_k<<<(NT + 255) / 256, 256>>>(beta_c, beta_d, pRsAdj, pCsAdj, pRsC, pRsD,
                                          pDx, pDy, pDx1, pDy1, out);

    // agg_cell_lp / agg_drug_lp
    scale_mat_k<<<dim3((ND + 255) / 256, NC), 256>>>(adj, pDx, pDy, ND, out + OUT0);
    scale_mat_k<<<dim3((NC + 255) / 256, ND), 256>>>(pAdjT, pDy, pDx, NC, out + OUT1);

    // agg_adj_lp (4 regions)
    agg_TL_k<<<dim3((NC + 255) / 256, NC), 256>>>(pC, pMuC, pIsC, gamma_c, beta_c, pDx1, pDy1, out);
    agg_TR_k<<<dim3((ND + 255) / 256, NC), 256>>>(adj, pDx1, pDy1, out);
    agg_BL_k<<<dim3((NC + 255) / 256, ND), 256>>>(pAdjT, pDx1, pDy1, out);
    agg_BR_k<<<dim3((ND + 255) / 256, ND), 256>>>(pD, pMuD, pIsD, gamma_d, beta_d, pDx1, pDy1, out);
}